// round 10
// baseline (speedup 1.0000x reference)
#include <cuda_runtime.h>
#include <cuda_bf16.h>
#include <math.h>

// ---------------- problem constants ----------------
#define NB    64
#define NS    32
#define BS    2048            // NB*NS frames
#define D_MODEL 128
#define D_STATE 32
#define D_CONV  4
#define D_INNER 256
#define DT_RANK 8
#define CNN_OUT 3136
#define NA    18
#define INV255 (1.0f/255.0f)

typedef unsigned long long ull;
typedef unsigned int uint;

// ---------------- scratch (static device globals; no allocation) ----------------
__device__ __nv_bfloat16 g_a1h[(size_t)BS*12800];   // conv1 out NHWC hi [img][px400][c32]
__device__ __nv_bfloat16 g_a1l[(size_t)BS*12800];   // conv1 out NHWC lo
__device__ __nv_bfloat16 g_a2h[(size_t)BS*5184];    // conv2 out NHWC hi [img][px81][c64]
__device__ __nv_bfloat16 g_a2l[(size_t)BS*5184];    // conv2 out NHWC lo
__device__ __nv_bfloat16 g_a3h[(size_t)BS*3136];    // conv3 out hi [img][oc*49+px]
__device__ __nv_bfloat16 g_a3l[(size_t)BS*3136];    // conv3 out lo
__device__ float g_featp[(size_t)14*BS*128];        // split-K partials
__device__ __nv_bfloat16 g_feath[(size_t)BS*128];   // feat bf16 hi plane
__device__ __nv_bfloat16 g_featl[(size_t)BS*128];   // feat bf16 lo plane
__device__ float g_xz  [(size_t)BS*512];
__device__ float g_u   [(size_t)BS*256];
__device__ float g_xdbl[(size_t)BS*72];
__device__ float g_dt  [(size_t)BS*256];
__device__ float g_yg  [NB*256];
// prepacked weights in mma B-fragment order: uint4 {b0hi, b1hi, b0lo, b1lo}
__device__ uint4 g_wp1[16*4*32];      // conv1: 16 k-steps x 4 n-tiles x 32 lanes
__device__ uint4 g_wp2[32*8*32];      // conv2: 32 x 8 x 32
__device__ uint4 g_wp3[36*8*32];      // conv3: 36 x 8 x 32
__device__ uint4 g_wpf[196*16*32];    // feat : 196 k-steps x 16 n-tiles x 32 lanes
__device__ uint4 g_wpi[8*64*32];      // in_proj: 8 k-steps x 64 n-tiles x 32 lanes

// ---------------- helpers ----------------
__device__ __forceinline__ void bfsplit(float v, __nv_bfloat16& h, __nv_bfloat16& l) {
    h = __float2bfloat16_rn(v);
    l = __float2bfloat16_rn(v - __bfloat162float(h));
}
__device__ __forceinline__ uint packbf2(__nv_bfloat16 a, __nv_bfloat16 b) {
    __nv_bfloat162 t; t.x = a; t.y = b;      // .x -> low 16 bits (lower k)
    return *reinterpret_cast<uint*>(&t);
}
__device__ __forceinline__ void mma_bf(float* d, uint a0, uint a1, uint a2, uint a3,
                                       uint b0, uint b1) {
    asm("mma.sync.aligned.m16n8k16.row.col.f32.bf16.bf16.f32 "
        "{%0,%1,%2,%3}, {%4,%5,%6,%7}, {%8,%9}, {%0,%1,%2,%3};"
        : "+f"(d[0]), "+f"(d[1]), "+f"(d[2]), "+f"(d[3])
        : "r"(a0), "r"(a1), "r"(a2), "r"(a3), "r"(b0), "r"(b1));
}

// ---------------- weight prepack (once per launch) ----------------
__global__ void prep_wpack(const float* __restrict__ w1,
                           const float* __restrict__ w2,
                           const float* __restrict__ w3,
                           const float* __restrict__ wf,
                           const float* __restrict__ wi) {
    int idx = blockIdx.x * 256 + threadIdx.x;
    float v[4];
    if (idx < 2048) {                         // conv1
        int lane = idx & 31, j = (idx >> 5) & 3, s = idx >> 7;
        int g = lane >> 2, tg = lane & 3, oc = j * 8 + g;
        int ky = s >> 1, cc = s & 1;
#pragma unroll
        for (int q = 0; q < 4; q++) {
            int r = (q < 2) ? tg * 2 + q : tg * 2 + 6 + q;   // tg*2,+1,+8,+9
            int kxl = r >> 2, c = r & 3;
            v[q] = w1[oc * 256 + c * 64 + ky * 8 + cc * 4 + kxl];
        }
        __nv_bfloat16 h[4], l[4];
#pragma unroll
        for (int q = 0; q < 4; q++) bfsplit(v[q], h[q], l[q]);
        g_wp1[idx] = make_uint4(packbf2(h[0],h[1]), packbf2(h[2],h[3]),
                                packbf2(l[0],l[1]), packbf2(l[2],l[3]));
    } else if (idx < 2048 + 8192) {           // conv2
        int i = idx - 2048;
        int lane = i & 31, j = (i >> 5) & 7, s = i >> 8;
        int g = lane >> 2, tg = lane & 3, oc = j * 8 + g;
        int tap = s >> 1, cc = s & 1;
        int ky = tap >> 2, kx = tap & 3;
#pragma unroll
        for (int q = 0; q < 4; q++) {
            int r = (q < 2) ? tg * 2 + q : tg * 2 + 6 + q;
            int c = cc * 16 + r;
            v[q] = w2[oc * 512 + c * 16 + ky * 4 + kx];
        }
        __nv_bfloat16 h[4], l[4];
#pragma unroll
        for (int q = 0; q < 4; q++) bfsplit(v[q], h[q], l[q]);
        g_wp2[i] = make_uint4(packbf2(h[0],h[1]), packbf2(h[2],h[3]),
                              packbf2(l[0],l[1]), packbf2(l[2],l[3]));
    } else if (idx < 2048 + 8192 + 9216) {    // conv3
        int i = idx - 10240;
        int lane = i & 31, j = (i >> 5) & 7, s = i >> 8;
        int g = lane >> 2, tg = lane & 3, oc = j * 8 + g;
        int tap = s >> 2, cc = s & 3;
        int ky = tap / 3, kx = tap % 3;
#pragma unroll
        for (int q = 0; q < 4; q++) {
            int r = (q < 2) ? tg * 2 + q : tg * 2 + 6 + q;
            int c = cc * 16 + r;
            v[q] = w3[oc * 576 + c * 9 + ky * 3 + kx];
        }
        __nv_bfloat16 h[4], l[4];
#pragma unroll
        for (int q = 0; q < 4; q++) bfsplit(v[q], h[q], l[q]);
        g_wp3[i] = make_uint4(packbf2(h[0],h[1]), packbf2(h[2],h[3]),
                              packbf2(l[0],l[1]), packbf2(l[2],l[3]));
    } else if (idx < 19456 + 100352) {        // feat: W[128][3136]
        int i = idx - 19456;
        int lane = i & 31, j = (i >> 5) & 15, s = i >> 9;
        int g = lane >> 2, tg = lane & 3, oc = j * 8 + g;
#pragma unroll
        for (int q = 0; q < 4; q++) {
            int r = (q < 2) ? tg * 2 + q : tg * 2 + 6 + q;
            v[q] = wf[oc * 3136 + s * 16 + r];
        }
        __nv_bfloat16 h[4], l[4];
#pragma unroll
        for (int q = 0; q < 4; q++) bfsplit(v[q], h[q], l[q]);
        g_wpf[i] = make_uint4(packbf2(h[0],h[1]), packbf2(h[2],h[3]),
                              packbf2(l[0],l[1]), packbf2(l[2],l[3]));
    } else if (idx < 119808 + 16384) {        // in_proj: W[512][128]
        int i = idx - 119808;
        int lane = i & 31, j = (i >> 5) & 63, s = i >> 11;
        int g = lane >> 2, tg = lane & 3, oc = j * 8 + g;
#pragma unroll
        for (int q = 0; q < 4; q++) {
            int r = (q < 2) ? tg * 2 + q : tg * 2 + 6 + q;
            v[q] = wi[oc * 128 + s * 16 + r];
        }
        __nv_bfloat16 h[4], l[4];
#pragma unroll
        for (int q = 0; q < 4; q++) bfsplit(v[q], h[q], l[q]);
        g_wpi[i] = make_uint4(packbf2(h[0],h[1]), packbf2(h[2],h[3]),
                              packbf2(l[0],l[1]), packbf2(l[2],l[3]));
    }
}

// ---------------- conv1: 4->32, 8x8, s4 | half-image blocks, 2 CTAs/SM ----------------
__global__ void __launch_bounds__(416, 2) conv1_mma(const float* __restrict__ x,
                                                    const float* __restrict__ bias) {
    extern __shared__ __nv_bfloat16 sm[];
    const int ELS = 14784;                    // 44*84*4 els per plane
    __nv_bfloat16* smh = sm;
    __nv_bfloat16* sml = sm + ELS;
    int img = blockIdx.x >> 1, half = blockIdx.x & 1;
    int y0 = half * 40;
    const float4* xin4 = (const float4*)(x + (size_t)img * 28224);
    for (int i = threadIdx.x; i < 3696; i += 416) {
        int c = i / 924, rr = i % 924;
        int ly = rr / 21, q = rr % 21;
        float4 v4 = xin4[c * 1764 + (y0 + ly) * 21 + q];
        float vv[4] = {v4.x, v4.y, v4.z, v4.w};
#pragma unroll
        for (int jj = 0; jj < 4; jj++) {
            int px = ly * 84 + q * 4 + jj;
            __nv_bfloat16 h, l;
            bfsplit(vv[jj] * INV255, h, l);
            smh[px * 4 + c] = h;
            sml[px * 4 + c] = l;
        }
    }
    __syncthreads();

    int warp = threadIdx.x >> 5, lane = threadIdx.x & 31;
    int g = lane >> 2, tg = lane & 3;
    int r0 = warp * 16 + g, r1 = r0 + 8;       // 0..207, valid < 200
    int rv0 = min(r0, 199), rv1 = min(r1, 199);
    int ba0 = (rv0 / 20) * 1344 + (rv0 % 20) * 16;
    int ba1 = (rv1 / 20) * 1344 + (rv1 % 20) * 16;

    float acc[4][4];
#pragma unroll
    for (int j = 0; j < 4; j++)
#pragma unroll
        for (int q = 0; q < 4; q++) acc[j][q] = 0.f;

    int s = 0;
#pragma unroll 1
    for (int ky = 0; ky < 8; ky++) {
#pragma unroll
        for (int cc = 0; cc < 2; cc++, s++) {
            int off = ky * 336 + cc * 16 + tg * 2;
            uint a0 = *(const uint*)(smh + ba0 + off);
            uint a1 = *(const uint*)(smh + ba1 + off);
            uint a2 = *(const uint*)(smh + ba0 + off + 8);
            uint a3 = *(const uint*)(smh + ba1 + off + 8);
            uint l0 = *(const uint*)(sml + ba0 + off);
            uint l1 = *(const uint*)(sml + ba1 + off);
            uint l2 = *(const uint*)(sml + ba0 + off + 8);
            uint l3 = *(const uint*)(sml + ba1 + off + 8);
            uint4 wq[4];
#pragma unroll
            for (int j = 0; j < 4; j++) wq[j] = g_wp1[(s * 4 + j) * 32 + lane];
#pragma unroll
            for (int j = 0; j < 4; j++) {
                mma_bf(acc[j], a0, a1, a2, a3, wq[j].x, wq[j].y);
                mma_bf(acc[j], a0, a1, a2, a3, wq[j].z, wq[j].w);
                mma_bf(acc[j], l0, l1, l2, l3, wq[j].x, wq[j].y);
            }
        }
    }
    size_t ob = (size_t)img * 12800 + half * 200 * 32;
#pragma unroll
    for (int j = 0; j < 4; j++) {
        int oc = j * 8 + tg * 2;
        float b0 = bias[oc], b1 = bias[oc + 1];
        if (r0 < 200) {
            float v0 = acc[j][0] + b0, v1 = acc[j][1] + b1;
            v0 = v0 > 0.f ? v0 : 0.f; v1 = v1 > 0.f ? v1 : 0.f;
            __nv_bfloat16 h0,l0_,h1,l1_;
            bfsplit(v0,h0,l0_); bfsplit(v1,h1,l1_);
            *(uint*)(g_a1h + ob + rv0 * 32 + oc) = packbf2(h0, h1);
            *(uint*)(g_a1l + ob + rv0 * 32 + oc) = packbf2(l0_, l1_);
        }
        if (r1 < 200) {
            float v0 = acc[j][2] + b0, v1 = acc[j][3] + b1;
            v0 = v0 > 0.f ? v0 : 0.f; v1 = v1 > 0.f ? v1 : 0.f;
            __nv_bfloat16 h0,l0_,h1,l1_;
            bfsplit(v0,h0,l0_); bfsplit(v1,h1,l1_);
            *(uint*)(g_a1h + ob + rv1 * 32 + oc) = packbf2(h0, h1);
            *(uint*)(g_a1l + ob + rv1 * 32 + oc) = packbf2(l0_, l1_);
        }
    }
}

// ---------------- conv2: 32->64, 4x4, s2 | smem-staged weights, dbl-buffered ----------------
__global__ void __launch_bounds__(192) conv2_mma(const float* __restrict__ bias) {
    extern __shared__ __nv_bfloat16 sm[];
    __nv_bfloat16* smh = sm;                 // 400*40 = 16000 el
    __nv_bfloat16* sml = sm + 16000;
    uint4* wb = (uint4*)(sm + 32000);        // 2 x 256 uint4 ring
    int img = blockIdx.x;
    for (int i = threadIdx.x; i < 3200; i += 192) {
        int px = i >> 3, cc = i & 7;
        ull vh = ((const ull*)g_a1h)[(size_t)img * 3200 + i];
        ull vl = ((const ull*)g_a1l)[(size_t)img * 3200 + i];
        *(ull*)(smh + px * 40 + cc * 4) = vh;
        *(ull*)(sml + px * 40 + cc * 4) = vl;
    }
    for (int i = threadIdx.x; i < 256; i += 192) wb[i] = g_wp2[i];
    __syncthreads();

    int warp = threadIdx.x >> 5, lane = threadIdx.x & 31;
    int g = lane >> 2, tg = lane & 3;
    int r0 = warp * 16 + g, r1 = r0 + 8;
    int p0 = min(r0, 80), p1 = min(r1, 80);
    int ba0 = ((p0 / 9) * 40 + (p0 % 9) * 2) * 40;
    int ba1 = ((p1 / 9) * 40 + (p1 % 9) * 2) * 40;

    float acc[8][4];
#pragma unroll
    for (int j = 0; j < 8; j++)
#pragma unroll
        for (int q = 0; q < 4; q++) acc[j][q] = 0.f;

    int s = 0;
#pragma unroll 1
    for (int ky = 0; ky < 4; ky++) {
#pragma unroll 1
        for (int kx = 0; kx < 4; kx++) {
            int toff = (ky * 20 + kx) * 40;
#pragma unroll
            for (int cc = 0; cc < 2; cc++, s++) {
                // prefetch next step's weight slab
                if (s + 1 < 32)
                    for (int i = threadIdx.x; i < 256; i += 192)
                        wb[((s + 1) & 1) * 256 + i] = g_wp2[(s + 1) * 256 + i];
                const uint4* wqp = wb + (s & 1) * 256;
                int off = toff + cc * 16 + tg * 2;
                uint a0 = *(const uint*)(smh + ba0 + off);
                uint a1 = *(const uint*)(smh + ba1 + off);
                uint a2 = *(const uint*)(smh + ba0 + off + 8);
                uint a3 = *(const uint*)(smh + ba1 + off + 8);
                uint l0 = *(const uint*)(sml + ba0 + off);
                uint l1 = *(const uint*)(sml + ba1 + off);
                uint l2 = *(const uint*)(sml + ba0 + off + 8);
                uint l3 = *(const uint*)(sml + ba1 + off + 8);
                uint4 wq[8];
#pragma unroll
                for (int j = 0; j < 8; j++) wq[j] = wqp[j * 32 + lane];
#pragma unroll
                for (int j = 0; j < 8; j++) {
                    mma_bf(acc[j], a0, a1, a2, a3, wq[j].x, wq[j].y);
                    mma_bf(acc[j], a0, a1, a2, a3, wq[j].z, wq[j].w);
                    mma_bf(acc[j], l0, l1, l2, l3, wq[j].x, wq[j].y);
                }
                __syncthreads();
            }
        }
    }
    size_t ob = (size_t)img * 5184;
#pragma unroll
    for (int j = 0; j < 8; j++) {
        int oc = j * 8 + tg * 2;
        float b0 = bias[oc], b1 = bias[oc + 1];
        if (r0 < 81) {
            float v0 = acc[j][0] + b0, v1 = acc[j][1] + b1;
            v0 = v0 > 0.f ? v0 : 0.f; v1 = v1 > 0.f ? v1 : 0.f;
            __nv_bfloat16 h0,l0_,h1,l1_;
            bfsplit(v0,h0,l0_); bfsplit(v1,h1,l1_);
            *(uint*)(g_a2h + ob + r0 * 64 + oc) = packbf2(h0, h1);
            *(uint*)(g_a2l + ob + r0 * 64 + oc) = packbf2(l0_, l1_);
        }
        if (r1 < 81) {
            float v0 = acc[j][2] + b0, v1 = acc[j][3] + b1;
            v0 = v0 > 0.f ? v0 : 0.f; v1 = v1 > 0.f ? v1 : 0.f;
            __nv_bfloat16 h0,l0_,h1,l1_;
            bfsplit(v0,h0,l0_); bfsplit(v1,h1,l1_);
            *(uint*)(g_a2h + ob + r1 * 64 + oc) = packbf2(h0, h1);
            *(uint*)(g_a2l + ob + r1 * 64 + oc) = packbf2(l0_, l1_);
        }
    }
}

// ---------------- conv3: 64->64, 3x3, s1 | smem-staged weights, dbl-buffered ----------------
__global__ void __launch_bounds__(416, 2) conv3_mma(const float* __restrict__ bias) {
    extern __shared__ __nv_bfloat16 sm[];
    const int PS = 5832;                      // 81*72 padded els per image
    __nv_bfloat16* smh = sm;
    __nv_bfloat16* sml = sm + 4 * PS;
    uint4* wb = (uint4*)(sm + 8 * PS);        // 2 x 256 uint4 ring (93312 B offset, 16B aligned)
    int img0 = blockIdx.x * 4;
    for (int i = threadIdx.x; i < 4 * 1296; i += 416) {
        int il = i / 1296, r = i % 1296;
        int px = r >> 4, cc = r & 15;
        ull vh = ((const ull*)g_a2h)[(size_t)(img0 + il) * 1296 + r];
        ull vl = ((const ull*)g_a2l)[(size_t)(img0 + il) * 1296 + r];
        *(ull*)(smh + il * PS + px * 72 + cc * 4) = vh;
        *(ull*)(sml + il * PS + px * 72 + cc * 4) = vl;
    }
    if (threadIdx.x < 256) wb[threadIdx.x] = g_wp3[threadIdx.x];
    __syncthreads();

    int warp = threadIdx.x >> 5, lane = threadIdx.x & 31;
    int g = lane >> 2, tg = lane & 3;
    int r0 = warp * 16 + g, r1 = r0 + 8;      // rows in 0..207; valid < 196
    int rv0 = min(r0, 195), rv1 = min(r1, 195);
    int il0 = rv0 / 49, px0 = rv0 - il0 * 49;
    int il1 = rv1 / 49, px1 = rv1 - il1 * 49;
    int ba0 = il0 * PS + ((px0 / 7) * 9 + (px0 % 7)) * 72;
    int ba1 = il1 * PS + ((px1 / 7) * 9 + (px1 % 7)) * 72;

    float acc[8][4];
#pragma unroll
    for (int j = 0; j < 8; j++)
#pragma unroll
        for (int q = 0; q < 4; q++) acc[j][q] = 0.f;

    int s = 0;
#pragma unroll 1
    for (int ky = 0; ky < 3; ky++) {
#pragma unroll 1
        for (int kx = 0; kx < 3; kx++) {
            int toff = (ky * 9 + kx) * 72;
#pragma unroll
            for (int cc = 0; cc < 4; cc++, s++) {
                if (threadIdx.x < 256 && s + 1 < 36)
                    wb[((s + 1) & 1) * 256 + threadIdx.x] = g_wp3[(s + 1) * 256 + threadIdx.x];
                const uint4* wqp = wb + (s & 1) * 256;
                int off = toff + cc * 16 + tg * 2;
                uint a0 = *(const uint*)(smh + ba0 + off);
                uint a1 = *(const uint*)(smh + ba1 + off);
                uint a2 = *(const uint*)(smh + ba0 + off + 8);
                uint a3 = *(const uint*)(smh + ba1 + off + 8);
                uint l0 = *(const uint*)(sml + ba0 + off);
                uint l1 = *(const uint*)(sml + ba1 + off);
                uint l2 = *(const uint*)(sml + ba0 + off + 8);
                uint l3 = *(const uint*)(sml + ba1 + off + 8);
                uint4 wq[8];
#pragma unroll
                for (int j = 0; j < 8; j++) wq[j] = wqp[j * 32 + lane];
#pragma unroll
                for (int j = 0; j < 8; j++) {
                    mma_bf(acc[j], a0, a1, a2, a3, wq[j].x, wq[j].y);
                    mma_bf(acc[j], a0, a1, a2, a3, wq[j].z, wq[j].w);
                    mma_bf(acc[j], l0, l1, l2, l3, wq[j].x, wq[j].y);
                }
                __syncthreads();
            }
        }
    }
    // epilogue: bias + relu + bf16 split, layout [img][oc*49 + px]
#pragma unroll
    for (int j = 0; j < 8; j++) {
        int oc = j * 8 + tg * 2;
        float b0 = bias[oc], b1 = bias[oc + 1];
        if (r0 < 196) {
            size_t ob = (size_t)(img0 + il0) * 3136;
            float v0 = acc[j][0] + b0, v1 = acc[j][1] + b1;
            v0 = v0 > 0.f ? v0 : 0.f; v1 = v1 > 0.f ? v1 : 0.f;
            __nv_bfloat16 h, l;
            bfsplit(v0, h, l);
            g_a3h[ob + (size_t)oc * 49 + px0] = h;
            g_a3l[ob + (size_t)oc * 49 + px0] = l;
            bfsplit(v1, h, l);
            g_a3h[ob + (size_t)(oc + 1) * 49 + px0] = h;
            g_a3l[ob + (size_t)(oc + 1) * 49 + px0] = l;
        }
        if (r1 < 196) {
            size_t ob = (size_t)(img0 + il1) * 3136;
            float v0 = acc[j][2] + b0, v1 = acc[j][3] + b1;
            v0 = v0 > 0.f ? v0 : 0.f; v1 = v1 > 0.f ? v1 : 0.f;
            __nv_bfloat16 h, l;
            bfsplit(v0, h, l);
            g_a3h[ob + (size_t)oc * 49 + px1] = h;
            g_a3l[ob + (size_t)oc * 49 + px1] = l;
            bfsplit(v1, h, l);
            g_a3h[ob + (size_t)(oc + 1) * 49 + px1] = h;
            g_a3l[ob + (size_t)(oc + 1) * 49 + px1] = l;
        }
    }
}

// ---------------- feat split-K: (2048 x 3136) @ (128 x 3136)^T ----------------
__global__ void __launch_bounds__(64) feat_mma(void) {
    int mb = blockIdx.x, kc = blockIdx.y;
    int row0 = mb * 16;
    int warp = threadIdx.x >> 5, lane = threadIdx.x & 31;
    int g = lane >> 2, tg = lane & 3;
    int r0 = row0 + g, r1 = r0 + 8;
    const __nv_bfloat16* ah0 = g_a3h + (size_t)r0 * 3136;
    const __nv_bfloat16* ah1 = g_a3h + (size_t)r1 * 3136;
    const __nv_bfloat16* al0 = g_a3l + (size_t)r0 * 3136;
    const __nv_bfloat16* al1 = g_a3l + (size_t)r1 * 3136;

    float acc[8][4];
#pragma unroll
    for (int j = 0; j < 8; j++)
#pragma unroll
        for (int q = 0; q < 4; q++) acc[j][q] = 0.f;

    int s0 = kc * 14;
#pragma unroll 2
    for (int si = 0; si < 14; si++) {
        int s = s0 + si;
        int off = s * 16 + tg * 2;
        uint a0 = *(const uint*)(ah0 + off);
        uint a1 = *(const uint*)(ah1 + off);
        uint a2 = *(const uint*)(ah0 + off + 8);
        uint a3 = *(const uint*)(ah1 + off + 8);
        uint l0 = *(const uint*)(al0 + off);
        uint l1 = *(const uint*)(al1 + off);
        uint l2 = *(const uint*)(al0 + off + 8);
        uint l3 = *(const uint*)(al1 + off + 8);
        uint4 wq[8];
#pragma unroll
        for (int j = 0; j < 8; j++) wq[j] = g_wpf[(s * 16 + warp * 8 + j) * 32 + lane];
#pragma unroll
        for (int j = 0; j < 8; j++) {
            mma_bf(acc[j], a0, a1, a2, a3, wq[j].x, wq[j].y);
            mma_bf(acc[j], a0, a1, a2, a3, wq[j].z, wq[j].w);
            mma_bf(acc[j], l0, l1, l2, l3, wq[j].x, wq[j].y);
        }
    }
    float* dst = g_featp + (size_t)kc * BS * 128;
#pragma unroll
    for (int j = 0; j < 8; j++) {
        int col = (warp * 8 + j) * 8 + tg * 2;
        dst[(size_t)r0 * 128 + col]     = acc[j][0];
        dst[(size_t)r0 * 128 + col + 1] = acc[j][1];
        dst[(size_t)r1 * 128 + col]     = acc[j][2];
        dst[(size_t)r1 * 128 + col + 1] = acc[j][3];
    }
}

// sum 14 partials + bias; emit bf16 hi/lo planes for in_proj mma
__global__ void feat_reduce(const float* __restrict__ bias) {
    int idx = blockIdx.x * 256 + threadIdx.x;
    if (idx >= BS * 128) return;
    float s = bias[idx & 127];
#pragma unroll
    for (int kc = 0; kc < 14; kc++) s += g_featp[(size_t)kc * BS * 128 + idx];
    __nv_bfloat16 h, l;
    bfsplit(s, h, l);
    g_feath[idx] = h;
    g_featl[idx] = l;
}

// ---------------- in_proj: (2048 x 128) @ (512 x 128)^T, no bias ----------------
__global__ void __launch_bounds__(128) inproj_mma(void) {
    int mb = blockIdx.x, nb = blockIdx.y;
    int row0 = mb * 16;
    int warp = threadIdx.x >> 5, lane = threadIdx.x & 31;
    int g = lane >> 2, tg = lane & 3;
    int jbase = nb * 32 + warp * 8;
    int r0 = row0 + g, r1 = r0 + 8;
    const __nv_bfloat16* ah0 = g_feath + (size_t)r0 * 128;
    const __nv_bfloat16* ah1 = g_feath + (size_t)r1 * 128;
    const __nv_bfloat16* al0 = g_featl + (size_t)r0 * 128;
    const __nv_bfloat16* al1 = g_featl + (size_t)r1 * 128;

    float acc[8][4];
#pragma unroll
    for (int j = 0; j < 8; j++)
#pragma unroll
        for (int q = 0; q < 4; q++) acc[j][q] = 0.f;

#pragma unroll
    for (int s = 0; s < 8; s++) {
        int off = s * 16 + tg * 2;
        uint a0 = *(const uint*)(ah0 + off);
        uint a1 = *(const uint*)(ah1 + off);
        uint a2 = *(const uint*)(ah0 + off + 8);
        uint a3 = *(const uint*)(ah1 + off + 8);
        uint l0 = *(const uint*)(al0 + off);
        uint l1 = *(const uint*)(al1 + off);
        uint l2 = *(const uint*)(al0 + off + 8);
        uint l3 = *(const uint*)(al1 + off + 8);
        uint4 wq[8];
#pragma unroll
        for (int j = 0; j < 8; j++) wq[j] = g_wpi[(s * 64 + jbase + j) * 32 + lane];
#pragma unroll
        for (int j = 0; j < 8; j++) {
            mma_bf(acc[j], a0, a1, a2, a3, wq[j].x, wq[j].y);
            mma_bf(acc[j], a0, a1, a2, a3, wq[j].z, wq[j].w);
            mma_bf(acc[j], l0, l1, l2, l3, wq[j].x, wq[j].y);
        }
    }
#pragma unroll
    for (int j = 0; j < 8; j++) {
        int col = (jbase + j) * 8 + tg * 2;
        g_xz[(size_t)r0 * 512 + col]     = acc[j][0];
        g_xz[(size_t)r0 * 512 + col + 1] = acc[j][1];
        g_xz[(size_t)r1 * 512 + col]     = acc[j][2];
        g_xz[(size_t)r1 * 512 + col + 1] = acc[j][3];
    }
}

// ---------------- causal depthwise conv1d + silu ----------------
__global__ void conv1d_silu(const float* __restrict__ w, const float* __restrict__ b) {
    int idx = blockIdx.x * 256 + threadIdx.x;
    if (idx >= BS * 256) return;
    int bs = idx >> 8;
    int d  = idx & 255;
    int bb = bs >> 5, s = bs & 31;
    float acc = b[d];
#pragma unroll
    for (int k = 0; k < 4; k++) {
        int si = s - 3 + k;
        if (si >= 0) acc += g_xz[(size_t)(bb * 32 + si) * 512 + d] * w[d * 4 + k];
    }
    g_u[(size_t)bs * 256 + d] = acc / (1.f + __expf(-acc));
}

// ---------------- fused x_proj + dt: 32 rows/block, 256 threads ----------------
__global__ void __launch_bounds__(256) xproj_dt_kernel(const float* __restrict__ xw,
                                                       const float* __restrict__ dw,
                                                       const float* __restrict__ db) {
    __shared__ float As[32][257];
    __shared__ float dts[32][8];
    int row0 = blockIdx.x * 32;
    for (int i = threadIdx.x; i < 2048; i += 256) {
        int r = i >> 6, c4 = i & 63;
        float4 v = ((const float4*)(g_u + (size_t)(row0 + r) * 256))[c4];
        As[r][c4 * 4 + 0] = v.x; As[r][c4 * 4 + 1] = v.y;
        As[r][c4 * 4 + 2] = v.z; As[r][c4 * 4 + 3] = v.w;
    }
    __syncthreads();
    int r = threadIdx.x & 31, cg = threadIdx.x >> 5;
    float acc[9];
#pragma unroll
    for (int j = 0; j < 9; j++) acc[j] = 0.f;
#pragma unroll 4
    for (int k = 0; k < 256; k++) {
        float a = As[r][k];
#pragma unroll
        for (int j = 0; j < 9; j++) acc[j] += a * xw[(size_t)(cg * 9 + j) * 256 + k];
    }
    size_t orow = (size_t)(row0 + r) * 72;
#pragma unroll
    for (int j = 0; j < 9; j++) {
        int c = cg * 9 + j;
        g_xdbl[orow + c] = acc[j];
        if (c < 8) dts[r][c] = acc[j];
    }
    __syncthreads();
    int r2 = threadIdx.x >> 3, dbase = (threadIdx.x & 7) * 32;
    float a0 = dts[r2][0], a1 = dts[r2][1], a2 = dts[r2][2], a3 = dts[r2][3];
    float a4 = dts[r2][4], a5 = dts[r2][5], a6 = dts[r2][6], a7 = dts[r2][7];
    size_t drow = (size_t)(row0 + r2) * 256;
#pragma unroll 4
    for (int d = 0; d < 32; d++) {
        const float* wp = dw + (size_t)(dbase + d) * 8;
        float s = db[dbase + d]
                + a0 * wp[0] + a1 * wp[1] + a2 * wp[2] + a3 * wp[3]
                + a4 * wp[4] + a5 * wp[5] + a6 * wp[6] + a7 * wp[7];
        g_dt[drow + dbase + d] = (s > 20.f) ? s : log1pf(__expf(s));
    }
}

// ---------------- selective scan; contract with C only at t=S-1 ----------------
__global__ void scan_kernel(const float* __restrict__ A_log, const float* __restrict__ Dv) {
    int w = blockIdx.x * 8 + (threadIdx.x >> 5);
    int lane = threadIdx.x & 31;
    int bb = w >> 8, d = w & 255;
    float An = -__expf(A_log[d * 32 + lane]);
    float h = 0.f;
#pragma unroll 4
    for (int t = 0; t < 32; t++) {
        size_t bs = (size_t)(bb * 32 + t);
        float dtv = g_dt[bs * 256 + d];
        float uv  = g_u [bs * 256 + d];
        float Bv  = g_xdbl[bs * 72 + 8 + lane];
        h = __expf(dtv * An) * h + (dtv * uv) * Bv;
    }
    size_t bs_last = (size_t)(bb * 32 + 31);
    float Cv = g_xdbl[bs_last * 72 + 40 + lane];
    float y = h * Cv;
#pragma unroll
    for (int o = 16; o; o >>= 1) y += __shfl_xor_sync(0xffffffffu, y, o);
    if (lane == 0) {
        float ul = g_u[bs_last * 256 + d];
        y += Dv[d] * ul;
        float z = g_xz[bs_last * 512 + 256 + d];
        y *= z / (1.f + __expf(-z));
        g_yg[bb * 256 + d] = y;
    }
}

// ---------------- heads: out_proj (last step) + fc1 + fc2 + q ----------------
__global__ void __launch_bounds__(128) heads_kernel(
        const float* __restrict__ op_w,
        const float* __restrict__ fc1_w, const float* __restrict__ fc1_b,
        const float* __restrict__ fc2_w, const float* __restrict__ fc2_b,
        const float* __restrict__ q_w,  const float* __restrict__ q_b,
        float* __restrict__ out) {
    int b = blockIdx.x, tid = threadIdx.x;
    __shared__ float yg[256], lat[128], h1[128], h2[128];
    yg[tid]       = g_yg[b * 256 + tid];
    yg[tid + 128] = g_yg[b * 256 + tid + 128];
    __syncthreads();
    float acc = 0.f;
#pragma unroll 8
    for (int k = 0; k < 256; k++) acc += op_w[tid * 256 + k] * yg[k];
    lat[tid] = acc;
    out[NB * NA + b * 128 + tid] = acc;
    __syncthreads();
    acc = fc1_b[tid];
#pragma unroll 8
    for (int k = 0; k < 128; k++) acc += fc1_w[tid * 128 + k] * lat[k];
    h1[tid] = acc > 0.f ? acc : 0.f;
    __syncthreads();
    acc = fc2_b[tid];
#pragma unroll 8
    for (int k = 0; k < 128; k++) acc += fc2_w[tid * 128 + k] * h1[k];
    h2[tid] = acc > 0.f ? acc : 0.f;
    __syncthreads();
    if (tid < NA) {
        acc = q_b[tid];
#pragma unroll 8
        for (int k = 0; k < 128; k++) acc += q_w[tid * 128 + k] * h2[k];
        out[b * NA + tid] = acc;
    }
}

// ---------------- host launcher ----------------
extern "C" void kernel_launch(void* const* d_in, const int* in_sizes, int n_in,
                              void* d_out, int out_size) {
    const float* x         = (const float*)d_in[0];
    const float* conv1_w   = (const float*)d_in[1];
    const float* conv1_b   = (const float*)d_in[2];
    const float* conv2_w   = (const float*)d_in[3];
    const float* conv2_b   = (const float*)d_in[4];
    const float* conv3_w   = (const float*)d_in[5];
    const float* conv3_b   = (const float*)d_in[6];
    const float* feat_w    = (const float*)d_in[7];
    const float* feat_b    = (const float*)d_in[8];
    const float* in_proj_w = (const float*)d_in[9];
    const float* conv1d_w  = (const float*)d_in[10];
    const float* conv1d_b  = (const float*)d_in[11];
    const float* x_proj_w  = (const float*)d_in[12];
    const float* dt_proj_w = (const float*)d_in[13];
    const float* dt_proj_b = (const float*)d_in[14];
    const float* A_log     = (const float*)d_in[15];
    const float* Dvec      = (const float*)d_in[16];
    const float* out_proj_w= (const float*)d_in[17];
    const float* fc1_w     = (const float*)d_in[18];
    const float* fc1_b     = (const float*)d_in[19];
    const float* fc2_w     = (const float*)d_in[20];
    const float* fc2_b     = (const float*)d_in[21];
    const float* q_w       = (const float*)d_in[22];
    const float* q_b       = (const float*)d_in[23];
    float* out = (float*)d_out;

    cudaFuncSetAttribute(conv1_mma, cudaFuncAttributeMaxDynamicSharedMemorySize, 59136);
    cudaFuncSetAttribute(conv2_mma, cudaFuncAttributeMaxDynamicSharedMemorySize, 72192);
    cudaFuncSetAttribute(conv3_mma, cudaFuncAttributeMaxDynamicSharedMemorySize, 101504);

    prep_wpack<<<532, 256>>>(conv1_w, conv2_w, conv3_w, feat_w, in_proj_w);
    conv1_mma<<<BS * 2, 416, 59136>>>(x, conv1_b);
    conv2_mma<<<BS, 192, 72192>>>(conv2_b);
    conv3_mma<<<BS / 4, 416, 101504>>>(conv3_b);

    // feat: split-K tensor-core GEMM + reduce (emits bf16 hi/lo planes)
    feat_mma<<<dim3(128, 14), 64>>>();
    feat_reduce<<<(BS * 128 + 255) / 256, 256>>>(feat_b);
    // in_proj: tensor-core mma
    inproj_mma<<<dim3(128, 2), 128>>>();
    conv1d_silu<<<(BS * 256 + 255) / 256, 256>>>(conv1d_w, conv1d_b);
    // fused x_proj + dt
    xproj_dt_kernel<<<64, 256>>>(x_proj_w, dt_proj_w, dt_proj_b);
    scan_kernel<<<BS, 256>>>(A_log, Dvec);
    heads_kernel<<<NB, 128>>>(out_proj_w, fc1_w, fc1_b, fc2_w, fc2_b, q_w, q_b, out);
}

// round 11
// speedup vs baseline: 1.1071x; 1.1071x over previous
#include <cuda_runtime.h>
#include <cuda_bf16.h>
#include <math.h>

// ---------------- problem constants ----------------
#define NB    64
#define NS    32
#define BS    2048            // NB*NS frames
#define D_MODEL 128
#define D_STATE 32
#define D_CONV  4
#define D_INNER 256
#define DT_RANK 8
#define CNN_OUT 3136
#define NA    18
#define INV255 (1.0f/255.0f)

typedef unsigned long long ull;
typedef unsigned int uint;

// ---------------- scratch (static device globals; no allocation) ----------------
__device__ __nv_bfloat16 g_a1h[(size_t)BS*12800];   // conv1 out NHWC hi [img][px400][c32]
__device__ __nv_bfloat16 g_a1l[(size_t)BS*12800];   // conv1 out NHWC lo
__device__ __nv_bfloat16 g_a2h[(size_t)BS*5184];    // conv2 out NHWC hi [img][px81][c64]
__device__ __nv_bfloat16 g_a2l[(size_t)BS*5184];    // conv2 out NHWC lo
__device__ __nv_bfloat16 g_a3h[(size_t)BS*3136];    // conv3 out hi [img][oc*49+px]
__device__ __nv_bfloat16 g_a3l[(size_t)BS*3136];    // conv3 out lo
__device__ float g_featp[(size_t)14*BS*128];        // split-K partials
__device__ __nv_bfloat16 g_feath[(size_t)BS*128];   // feat bf16 hi plane
__device__ __nv_bfloat16 g_featl[(size_t)BS*128];   // feat bf16 lo plane
__device__ float g_xz  [(size_t)BS*512];
__device__ float g_u   [(size_t)BS*256];
__device__ float g_xdbl[(size_t)BS*72];
__device__ float g_dt  [(size_t)BS*256];
__device__ float g_yg  [NB*256];
// prepacked weights in mma B-fragment order: uint4 {b0hi, b1hi, b0lo, b1lo}
__device__ uint4 g_wp1[16*4*32];      // conv1: 16 k-steps x 4 n-tiles x 32 lanes
__device__ uint4 g_wp2[32*8*32];      // conv2: 32 x 8 x 32
__device__ uint4 g_wp3[36*8*32];      // conv3: 36 x 8 x 32
__device__ uint4 g_wpf[196*16*32];    // feat : 196 k-steps x 16 n-tiles x 32 lanes
__device__ uint4 g_wpi[8*64*32];      // in_proj: 8 k-steps x 64 n-tiles x 32 lanes

// ---------------- helpers ----------------
__device__ __forceinline__ void bfsplit(float v, __nv_bfloat16& h, __nv_bfloat16& l) {
    h = __float2bfloat16_rn(v);
    l = __float2bfloat16_rn(v - __bfloat162float(h));
}
__device__ __forceinline__ uint packbf2(__nv_bfloat16 a, __nv_bfloat16 b) {
    __nv_bfloat162 t; t.x = a; t.y = b;      // .x -> low 16 bits (lower k)
    return *reinterpret_cast<uint*>(&t);
}
__device__ __forceinline__ void mma_bf(float* d, uint a0, uint a1, uint a2, uint a3,
                                       uint b0, uint b1) {
    asm("mma.sync.aligned.m16n8k16.row.col.f32.bf16.bf16.f32 "
        "{%0,%1,%2,%3}, {%4,%5,%6,%7}, {%8,%9}, {%0,%1,%2,%3};"
        : "+f"(d[0]), "+f"(d[1]), "+f"(d[2]), "+f"(d[3])
        : "r"(a0), "r"(a1), "r"(a2), "r"(a3), "r"(b0), "r"(b1));
}

// ---------------- weight prepack (once per launch) ----------------
__global__ void prep_wpack(const float* __restrict__ w1,
                           const float* __restrict__ w2,
                           const float* __restrict__ w3,
                           const float* __restrict__ wf,
                           const float* __restrict__ wi) {
    int idx = blockIdx.x * 256 + threadIdx.x;
    float v[4];
    if (idx < 2048) {                         // conv1
        int lane = idx & 31, j = (idx >> 5) & 3, s = idx >> 7;
        int g = lane >> 2, tg = lane & 3, oc = j * 8 + g;
        int ky = s >> 1, cc = s & 1;
#pragma unroll
        for (int q = 0; q < 4; q++) {
            int r = (q < 2) ? tg * 2 + q : tg * 2 + 6 + q;   // tg*2,+1,+8,+9
            int kxl = r >> 2, c = r & 3;
            v[q] = w1[oc * 256 + c * 64 + ky * 8 + cc * 4 + kxl];
        }
        __nv_bfloat16 h[4], l[4];
#pragma unroll
        for (int q = 0; q < 4; q++) bfsplit(v[q], h[q], l[q]);
        g_wp1[idx] = make_uint4(packbf2(h[0],h[1]), packbf2(h[2],h[3]),
                                packbf2(l[0],l[1]), packbf2(l[2],l[3]));
    } else if (idx < 2048 + 8192) {           // conv2
        int i = idx - 2048;
        int lane = i & 31, j = (i >> 5) & 7, s = i >> 8;
        int g = lane >> 2, tg = lane & 3, oc = j * 8 + g;
        int tap = s >> 1, cc = s & 1;
        int ky = tap >> 2, kx = tap & 3;
#pragma unroll
        for (int q = 0; q < 4; q++) {
            int r = (q < 2) ? tg * 2 + q : tg * 2 + 6 + q;
            int c = cc * 16 + r;
            v[q] = w2[oc * 512 + c * 16 + ky * 4 + kx];
        }
        __nv_bfloat16 h[4], l[4];
#pragma unroll
        for (int q = 0; q < 4; q++) bfsplit(v[q], h[q], l[q]);
        g_wp2[i] = make_uint4(packbf2(h[0],h[1]), packbf2(h[2],h[3]),
                              packbf2(l[0],l[1]), packbf2(l[2],l[3]));
    } else if (idx < 2048 + 8192 + 9216) {    // conv3
        int i = idx - 10240;
        int lane = i & 31, j = (i >> 5) & 7, s = i >> 8;
        int g = lane >> 2, tg = lane & 3, oc = j * 8 + g;
        int tap = s >> 2, cc = s & 3;
        int ky = tap / 3, kx = tap % 3;
#pragma unroll
        for (int q = 0; q < 4; q++) {
            int r = (q < 2) ? tg * 2 + q : tg * 2 + 6 + q;
            int c = cc * 16 + r;
            v[q] = w3[oc * 576 + c * 9 + ky * 3 + kx];
        }
        __nv_bfloat16 h[4], l[4];
#pragma unroll
        for (int q = 0; q < 4; q++) bfsplit(v[q], h[q], l[q]);
        g_wp3[i] = make_uint4(packbf2(h[0],h[1]), packbf2(h[2],h[3]),
                              packbf2(l[0],l[1]), packbf2(l[2],l[3]));
    } else if (idx < 19456 + 100352) {        // feat: W[128][3136]
        int i = idx - 19456;
        int lane = i & 31, j = (i >> 5) & 15, s = i >> 9;
        int g = lane >> 2, tg = lane & 3, oc = j * 8 + g;
#pragma unroll
        for (int q = 0; q < 4; q++) {
            int r = (q < 2) ? tg * 2 + q : tg * 2 + 6 + q;
            v[q] = wf[oc * 3136 + s * 16 + r];
        }
        __nv_bfloat16 h[4], l[4];
#pragma unroll
        for (int q = 0; q < 4; q++) bfsplit(v[q], h[q], l[q]);
        g_wpf[i] = make_uint4(packbf2(h[0],h[1]), packbf2(h[2],h[3]),
                              packbf2(l[0],l[1]), packbf2(l[2],l[3]));
    } else if (idx < 119808 + 16384) {        // in_proj: W[512][128]
        int i = idx - 119808;
        int lane = i & 31, j = (i >> 5) & 63, s = i >> 11;
        int g = lane >> 2, tg = lane & 3, oc = j * 8 + g;
#pragma unroll
        for (int q = 0; q < 4; q++) {
            int r = (q < 2) ? tg * 2 + q : tg * 2 + 6 + q;
            v[q] = wi[oc * 128 + s * 16 + r];
        }
        __nv_bfloat16 h[4], l[4];
#pragma unroll
        for (int q = 0; q < 4; q++) bfsplit(v[q], h[q], l[q]);
        g_wpi[i] = make_uint4(packbf2(h[0],h[1]), packbf2(h[2],h[3]),
                              packbf2(l[0],l[1]), packbf2(l[2],l[3]));
    }
}

// ---------------- conv1: 4->32, 8x8, s4 | half-image blocks, 2 CTAs/SM ----------------
__global__ void __launch_bounds__(416, 2) conv1_mma(const float* __restrict__ x,
                                                    const float* __restrict__ bias) {
    extern __shared__ __nv_bfloat16 sm[];
    const int ELS = 14784;                    // 44*84*4 els per plane
    __nv_bfloat16* smh = sm;
    __nv_bfloat16* sml = sm + ELS;
    int img = blockIdx.x >> 1, half = blockIdx.x & 1;
    int y0 = half * 40;
    const float4* xin4 = (const float4*)(x + (size_t)img * 28224);
    for (int i = threadIdx.x; i < 3696; i += 416) {
        int c = i / 924, rr = i % 924;
        int ly = rr / 21, q = rr % 21;
        float4 v4 = xin4[c * 1764 + (y0 + ly) * 21 + q];
        float vv[4] = {v4.x, v4.y, v4.z, v4.w};
#pragma unroll
        for (int jj = 0; jj < 4; jj++) {
            int px = ly * 84 + q * 4 + jj;
            __nv_bfloat16 h, l;
            bfsplit(vv[jj] * INV255, h, l);
            smh[px * 4 + c] = h;
            sml[px * 4 + c] = l;
        }
    }
    __syncthreads();

    int warp = threadIdx.x >> 5, lane = threadIdx.x & 31;
    int g = lane >> 2, tg = lane & 3;
    int r0 = warp * 16 + g, r1 = r0 + 8;       // 0..207, valid < 200
    int rv0 = min(r0, 199), rv1 = min(r1, 199);
    int ba0 = (rv0 / 20) * 1344 + (rv0 % 20) * 16;
    int ba1 = (rv1 / 20) * 1344 + (rv1 % 20) * 16;

    float acc[4][4];
#pragma unroll
    for (int j = 0; j < 4; j++)
#pragma unroll
        for (int q = 0; q < 4; q++) acc[j][q] = 0.f;

    int s = 0;
#pragma unroll 1
    for (int ky = 0; ky < 8; ky++) {
#pragma unroll
        for (int cc = 0; cc < 2; cc++, s++) {
            int off = ky * 336 + cc * 16 + tg * 2;
            uint a0 = *(const uint*)(smh + ba0 + off);
            uint a1 = *(const uint*)(smh + ba1 + off);
            uint a2 = *(const uint*)(smh + ba0 + off + 8);
            uint a3 = *(const uint*)(smh + ba1 + off + 8);
            uint l0 = *(const uint*)(sml + ba0 + off);
            uint l1 = *(const uint*)(sml + ba1 + off);
            uint l2 = *(const uint*)(sml + ba0 + off + 8);
            uint l3 = *(const uint*)(sml + ba1 + off + 8);
            uint4 wq[4];
#pragma unroll
            for (int j = 0; j < 4; j++) wq[j] = g_wp1[(s * 4 + j) * 32 + lane];
#pragma unroll
            for (int j = 0; j < 4; j++) {
                mma_bf(acc[j], a0, a1, a2, a3, wq[j].x, wq[j].y);
                mma_bf(acc[j], a0, a1, a2, a3, wq[j].z, wq[j].w);
                mma_bf(acc[j], l0, l1, l2, l3, wq[j].x, wq[j].y);
            }
        }
    }
    size_t ob = (size_t)img * 12800 + half * 200 * 32;
#pragma unroll
    for (int j = 0; j < 4; j++) {
        int oc = j * 8 + tg * 2;
        float b0 = bias[oc], b1 = bias[oc + 1];
        if (r0 < 200) {
            float v0 = acc[j][0] + b0, v1 = acc[j][1] + b1;
            v0 = v0 > 0.f ? v0 : 0.f; v1 = v1 > 0.f ? v1 : 0.f;
            __nv_bfloat16 h0,l0_,h1,l1_;
            bfsplit(v0,h0,l0_); bfsplit(v1,h1,l1_);
            *(uint*)(g_a1h + ob + rv0 * 32 + oc) = packbf2(h0, h1);
            *(uint*)(g_a1l + ob + rv0 * 32 + oc) = packbf2(l0_, l1_);
        }
        if (r1 < 200) {
            float v0 = acc[j][2] + b0, v1 = acc[j][3] + b1;
            v0 = v0 > 0.f ? v0 : 0.f; v1 = v1 > 0.f ? v1 : 0.f;
            __nv_bfloat16 h0,l0_,h1,l1_;
            bfsplit(v0,h0,l0_); bfsplit(v1,h1,l1_);
            *(uint*)(g_a1h + ob + rv1 * 32 + oc) = packbf2(h0, h1);
            *(uint*)(g_a1l + ob + rv1 * 32 + oc) = packbf2(l0_, l1_);
        }
    }
}

// ---------------- conv2: 32->64, 4x4, s2 | 12 warps: 6 m-tiles x 2 n-halves ----------------
__global__ void __launch_bounds__(384, 2) conv2_mma(const float* __restrict__ bias) {
    extern __shared__ __nv_bfloat16 sm[];
    __nv_bfloat16* smh = sm;                 // 400*40 = 16000 el
    __nv_bfloat16* sml = sm + 16000;
    int img = blockIdx.x;
    for (int i = threadIdx.x; i < 3200; i += 384) {
        int px = i >> 3, cc = i & 7;
        ull vh = ((const ull*)g_a1h)[(size_t)img * 3200 + i];
        ull vl = ((const ull*)g_a1l)[(size_t)img * 3200 + i];
        *(ull*)(smh + px * 40 + cc * 4) = vh;
        *(ull*)(sml + px * 40 + cc * 4) = vl;
    }
    __syncthreads();

    int warp = threadIdx.x >> 5, lane = threadIdx.x & 31;
    int mt = warp % 6, nh = warp / 6;        // m-tile 0..5, n-half 0..1
    int jbase = nh * 4;
    int g = lane >> 2, tg = lane & 3;
    int r0 = mt * 16 + g, r1 = r0 + 8;
    int p0 = min(r0, 80), p1 = min(r1, 80);
    int ba0 = ((p0 / 9) * 40 + (p0 % 9) * 2) * 40;
    int ba1 = ((p1 / 9) * 40 + (p1 % 9) * 2) * 40;

    float acc[4][4];
#pragma unroll
    for (int j = 0; j < 4; j++)
#pragma unroll
        for (int q = 0; q < 4; q++) acc[j][q] = 0.f;

    int s = 0;
#pragma unroll 1
    for (int ky = 0; ky < 4; ky++) {
#pragma unroll 1
        for (int kx = 0; kx < 4; kx++) {
            int toff = (ky * 20 + kx) * 40;
#pragma unroll
            for (int cc = 0; cc < 2; cc++, s++) {
                int off = toff + cc * 16 + tg * 2;
                uint a0 = *(const uint*)(smh + ba0 + off);
                uint a1 = *(const uint*)(smh + ba1 + off);
                uint a2 = *(const uint*)(smh + ba0 + off + 8);
                uint a3 = *(const uint*)(smh + ba1 + off + 8);
                uint l0 = *(const uint*)(sml + ba0 + off);
                uint l1 = *(const uint*)(sml + ba1 + off);
                uint l2 = *(const uint*)(sml + ba0 + off + 8);
                uint l3 = *(const uint*)(sml + ba1 + off + 8);
                uint4 wq[4];
#pragma unroll
                for (int j = 0; j < 4; j++)
                    wq[j] = g_wp2[(s * 8 + jbase + j) * 32 + lane];
#pragma unroll
                for (int j = 0; j < 4; j++) {
                    mma_bf(acc[j], a0, a1, a2, a3, wq[j].x, wq[j].y);
                    mma_bf(acc[j], a0, a1, a2, a3, wq[j].z, wq[j].w);
                    mma_bf(acc[j], l0, l1, l2, l3, wq[j].x, wq[j].y);
                }
            }
        }
    }
    size_t ob = (size_t)img * 5184;
#pragma unroll
    for (int j = 0; j < 4; j++) {
        int oc = (jbase + j) * 8 + tg * 2;
        float b0 = bias[oc], b1 = bias[oc + 1];
        if (r0 < 81) {
            float v0 = acc[j][0] + b0, v1 = acc[j][1] + b1;
            v0 = v0 > 0.f ? v0 : 0.f; v1 = v1 > 0.f ? v1 : 0.f;
            __nv_bfloat16 h0,l0_,h1,l1_;
            bfsplit(v0,h0,l0_); bfsplit(v1,h1,l1_);
            *(uint*)(g_a2h + ob + r0 * 64 + oc) = packbf2(h0, h1);
            *(uint*)(g_a2l + ob + r0 * 64 + oc) = packbf2(l0_, l1_);
        }
        if (r1 < 81) {
            float v0 = acc[j][2] + b0, v1 = acc[j][3] + b1;
            v0 = v0 > 0.f ? v0 : 0.f; v1 = v1 > 0.f ? v1 : 0.f;
            __nv_bfloat16 h0,l0_,h1,l1_;
            bfsplit(v0,h0,l0_); bfsplit(v1,h1,l1_);
            *(uint*)(g_a2h + ob + r1 * 64 + oc) = packbf2(h0, h1);
            *(uint*)(g_a2l + ob + r1 * 64 + oc) = packbf2(l0_, l1_);
        }
    }
}

// ---------------- conv3: 64->64, 3x3, s1 | smem-staged weights, dbl-buffered ----------------
__global__ void __launch_bounds__(416, 2) conv3_mma(const float* __restrict__ bias) {
    extern __shared__ __nv_bfloat16 sm[];
    const int PS = 5832;                      // 81*72 padded els per image
    __nv_bfloat16* smh = sm;
    __nv_bfloat16* sml = sm + 4 * PS;
    uint4* wb = (uint4*)(sm + 8 * PS);        // 2 x 256 uint4 ring
    int img0 = blockIdx.x * 4;
    for (int i = threadIdx.x; i < 4 * 1296; i += 416) {
        int il = i / 1296, r = i % 1296;
        int px = r >> 4, cc = r & 15;
        ull vh = ((const ull*)g_a2h)[(size_t)(img0 + il) * 1296 + r];
        ull vl = ((const ull*)g_a2l)[(size_t)(img0 + il) * 1296 + r];
        *(ull*)(smh + il * PS + px * 72 + cc * 4) = vh;
        *(ull*)(sml + il * PS + px * 72 + cc * 4) = vl;
    }
    if (threadIdx.x < 256) wb[threadIdx.x] = g_wp3[threadIdx.x];
    __syncthreads();

    int warp = threadIdx.x >> 5, lane = threadIdx.x & 31;
    int g = lane >> 2, tg = lane & 3;
    int r0 = warp * 16 + g, r1 = r0 + 8;      // rows in 0..207; valid < 196
    int rv0 = min(r0, 195), rv1 = min(r1, 195);
    int il0 = rv0 / 49, px0 = rv0 - il0 * 49;
    int il1 = rv1 / 49, px1 = rv1 - il1 * 49;
    int ba0 = il0 * PS + ((px0 / 7) * 9 + (px0 % 7)) * 72;
    int ba1 = il1 * PS + ((px1 / 7) * 9 + (px1 % 7)) * 72;

    float acc[8][4];
#pragma unroll
    for (int j = 0; j < 8; j++)
#pragma unroll
        for (int q = 0; q < 4; q++) acc[j][q] = 0.f;

    int s = 0;
#pragma unroll 1
    for (int ky = 0; ky < 3; ky++) {
#pragma unroll 1
        for (int kx = 0; kx < 3; kx++) {
            int toff = (ky * 9 + kx) * 72;
#pragma unroll
            for (int cc = 0; cc < 4; cc++, s++) {
                if (threadIdx.x < 256 && s + 1 < 36)
                    wb[((s + 1) & 1) * 256 + threadIdx.x] = g_wp3[(s + 1) * 256 + threadIdx.x];
                const uint4* wqp = wb + (s & 1) * 256;
                int off = toff + cc * 16 + tg * 2;
                uint a0 = *(const uint*)(smh + ba0 + off);
                uint a1 = *(const uint*)(smh + ba1 + off);
                uint a2 = *(const uint*)(smh + ba0 + off + 8);
                uint a3 = *(const uint*)(smh + ba1 + off + 8);
                uint l0 = *(const uint*)(sml + ba0 + off);
                uint l1 = *(const uint*)(sml + ba1 + off);
                uint l2 = *(const uint*)(sml + ba0 + off + 8);
                uint l3 = *(const uint*)(sml + ba1 + off + 8);
                uint4 wq[8];
#pragma unroll
                for (int j = 0; j < 8; j++) wq[j] = wqp[j * 32 + lane];
#pragma unroll
                for (int j = 0; j < 8; j++) {
                    mma_bf(acc[j], a0, a1, a2, a3, wq[j].x, wq[j].y);
                    mma_bf(acc[j], a0, a1, a2, a3, wq[j].z, wq[j].w);
                    mma_bf(acc[j], l0, l1, l2, l3, wq[j].x, wq[j].y);
                }
                __syncthreads();
            }
        }
    }
#pragma unroll
    for (int j = 0; j < 8; j++) {
        int oc = j * 8 + tg * 2;
        float b0 = bias[oc], b1 = bias[oc + 1];
        if (r0 < 196) {
            size_t ob = (size_t)(img0 + il0) * 3136;
            float v0 = acc[j][0] + b0, v1 = acc[j][1] + b1;
            v0 = v0 > 0.f ? v0 : 0.f; v1 = v1 > 0.f ? v1 : 0.f;
            __nv_bfloat16 h, l;
            bfsplit(v0, h, l);
            g_a3h[ob + (size_t)oc * 49 + px0] = h;
            g_a3l[ob + (size_t)oc * 49 + px0] = l;
            bfsplit(v1, h, l);
            g_a3h[ob + (size_t)(oc + 1) * 49 + px0] = h;
            g_a3l[ob + (size_t)(oc + 1) * 49 + px0] = l;
        }
        if (r1 < 196) {
            size_t ob = (size_t)(img0 + il1) * 3136;
            float v0 = acc[j][2] + b0, v1 = acc[j][3] + b1;
            v0 = v0 > 0.f ? v0 : 0.f; v1 = v1 > 0.f ? v1 : 0.f;
            __nv_bfloat16 h, l;
            bfsplit(v0, h, l);
            g_a3h[ob + (size_t)oc * 49 + px1] = h;
            g_a3l[ob + (size_t)oc * 49 + px1] = l;
            bfsplit(v1, h, l);
            g_a3h[ob + (size_t)(oc + 1) * 49 + px1] = h;
            g_a3l[ob + (size_t)(oc + 1) * 49 + px1] = l;
        }
    }
}

// ---------------- feat split-K: (2048 x 3136) @ (128 x 3136)^T ----------------
__global__ void __launch_bounds__(64) feat_mma(void) {
    int mb = blockIdx.x, kc = blockIdx.y;
    int row0 = mb * 16;
    int warp = threadIdx.x >> 5, lane = threadIdx.x & 31;
    int g = lane >> 2, tg = lane & 3;
    int r0 = row0 + g, r1 = r0 + 8;
    const __nv_bfloat16* ah0 = g_a3h + (size_t)r0 * 3136;
    const __nv_bfloat16* ah1 = g_a3h + (size_t)r1 * 3136;
    const __nv_bfloat16* al0 = g_a3l + (size_t)r0 * 3136;
    const __nv_bfloat16* al1 = g_a3l + (size_t)r1 * 3136;

    float acc[8][4];
#pragma unroll
    for (int j = 0; j < 8; j++)
#pragma unroll
        for (int q = 0; q < 4; q++) acc[j][q] = 0.f;

    int s0 = kc * 14;
#pragma unroll 2
    for (int si = 0; si < 14; si++) {
        int s = s0 + si;
        int off = s * 16 + tg * 2;
        uint a0 = *(const uint*)(ah0 + off);
        uint a1 = *(const uint*)(ah1 + off);
        uint a2 = *(const uint*)(ah0 + off + 8);
        uint a3 = *(const uint*)(ah1 + off + 8);
        uint l0 = *(const uint*)(al0 + off);
        uint l1 = *(const uint*)(al1 + off);
        uint l2 = *(const uint*)(al0 + off + 8);
        uint l3 = *(const uint*)(al1 + off + 8);
        uint4 wq[8];
#pragma unroll
        for (int j = 0; j < 8; j++) wq[j] = g_wpf[(s * 16 + warp * 8 + j) * 32 + lane];
#pragma unroll
        for (int j = 0; j < 8; j++) {
            mma_bf(acc[j], a0, a1, a2, a3, wq[j].x, wq[j].y);
            mma_bf(acc[j], a0, a1, a2, a3, wq[j].z, wq[j].w);
            mma_bf(acc[j], l0, l1, l2, l3, wq[j].x, wq[j].y);
        }
    }
    float* dst = g_featp + (size_t)kc * BS * 128;
#pragma unroll
    for (int j = 0; j < 8; j++) {
        int col = (warp * 8 + j) * 8 + tg * 2;
        dst[(size_t)r0 * 128 + col]     = acc[j][0];
        dst[(size_t)r0 * 128 + col + 1] = acc[j][1];
        dst[(size_t)r1 * 128 + col]     = acc[j][2];
        dst[(size_t)r1 * 128 + col + 1] = acc[j][3];
    }
}

// sum 14 partials + bias; emit bf16 hi/lo planes for in_proj mma
__global__ void feat_reduce(const float* __restrict__ bias) {
    int idx = blockIdx.x * 256 + threadIdx.x;
    if (idx >= BS * 128) return;
    float s = bias[idx & 127];
#pragma unroll
    for (int kc = 0; kc < 14; kc++) s += g_featp[(size_t)kc * BS * 128 + idx];
    __nv_bfloat16 h, l;
    bfsplit(s, h, l);
    g_feath[idx] = h;
    g_featl[idx] = l;
}

// ---------------- in_proj: (2048 x 128) @ (512 x 128)^T, no bias ----------------
__global__ void __launch_bounds__(128) inproj_mma(void) {
    int mb = blockIdx.x, nb = blockIdx.y;
    int row0 = mb * 16;
    int warp = threadIdx.x >> 5, lane = threadIdx.x & 31;
    int g = lane >> 2, tg = lane & 3;
    int jbase = nb * 32 + warp * 8;
    int r0 = row0 + g, r1 = r0 + 8;
    const __nv_bfloat16* ah0 = g_feath + (size_t)r0 * 128;
    const __nv_bfloat16* ah1 = g_feath + (size_t)r1 * 128;
    const __nv_bfloat16* al0 = g_featl + (size_t)r0 * 128;
    const __nv_bfloat16* al1 = g_featl + (size_t)r1 * 128;

    float acc[8][4];
#pragma unroll
    for (int j = 0; j < 8; j++)
#pragma unroll
        for (int q = 0; q < 4; q++) acc[j][q] = 0.f;

#pragma unroll
    for (int s = 0; s < 8; s++) {
        int off = s * 16 + tg * 2;
        uint a0 = *(const uint*)(ah0 + off);
        uint a1 = *(const uint*)(ah1 + off);
        uint a2 = *(const uint*)(ah0 + off + 8);
        uint a3 = *(const uint*)(ah1 + off + 8);
        uint l0 = *(const uint*)(al0 + off);
        uint l1 = *(const uint*)(al1 + off);
        uint l2 = *(const uint*)(al0 + off + 8);
        uint l3 = *(const uint*)(al1 + off + 8);
        uint4 wq[8];
#pragma unroll
        for (int j = 0; j < 8; j++) wq[j] = g_wpi[(s * 64 + jbase + j) * 32 + lane];
#pragma unroll
        for (int j = 0; j < 8; j++) {
            mma_bf(acc[j], a0, a1, a2, a3, wq[j].x, wq[j].y);
            mma_bf(acc[j], a0, a1, a2, a3, wq[j].z, wq[j].w);
            mma_bf(acc[j], l0, l1, l2, l3, wq[j].x, wq[j].y);
        }
    }
#pragma unroll
    for (int j = 0; j < 8; j++) {
        int col = (jbase + j) * 8 + tg * 2;
        g_xz[(size_t)r0 * 512 + col]     = acc[j][0];
        g_xz[(size_t)r0 * 512 + col + 1] = acc[j][1];
        g_xz[(size_t)r1 * 512 + col]     = acc[j][2];
        g_xz[(size_t)r1 * 512 + col + 1] = acc[j][3];
    }
}

// ---------------- causal depthwise conv1d + silu ----------------
__global__ void conv1d_silu(const float* __restrict__ w, const float* __restrict__ b) {
    int idx = blockIdx.x * 256 + threadIdx.x;
    if (idx >= BS * 256) return;
    int bs = idx >> 8;
    int d  = idx & 255;
    int bb = bs >> 5, s = bs & 31;
    float acc = b[d];
#pragma unroll
    for (int k = 0; k < 4; k++) {
        int si = s - 3 + k;
        if (si >= 0) acc += g_xz[(size_t)(bb * 32 + si) * 512 + d] * w[d * 4 + k];
    }
    g_u[(size_t)bs * 256 + d] = acc / (1.f + __expf(-acc));
}

// ---------------- fused x_proj + dt: 32 rows/block, 256 threads ----------------
__global__ void __launch_bounds__(256) xproj_dt_kernel(const float* __restrict__ xw,
                                                       const float* __restrict__ dw,
                                                       const float* __restrict__ db) {
    __shared__ float As[32][257];
    __shared__ float dts[32][8];
    int row0 = blockIdx.x * 32;
    for (int i = threadIdx.x; i < 2048; i += 256) {
        int r = i >> 6, c4 = i & 63;
        float4 v = ((const float4*)(g_u + (size_t)(row0 + r) * 256))[c4];
        As[r][c4 * 4 + 0] = v.x; As[r][c4 * 4 + 1] = v.y;
        As[r][c4 * 4 + 2] = v.z; As[r][c4 * 4 + 3] = v.w;
    }
    __syncthreads();
    int r = threadIdx.x & 31, cg = threadIdx.x >> 5;
    float acc[9];
#pragma unroll
    for (int j = 0; j < 9; j++) acc[j] = 0.f;
#pragma unroll 4
    for (int k = 0; k < 256; k++) {
        float a = As[r][k];
#pragma unroll
        for (int j = 0; j < 9; j++) acc[j] += a * xw[(size_t)(cg * 9 + j) * 256 + k];
    }
    size_t orow = (size_t)(row0 + r) * 72;
#pragma unroll
    for (int j = 0; j < 9; j++) {
        int c = cg * 9 + j;
        g_xdbl[orow + c] = acc[j];
        if (c < 8) dts[r][c] = acc[j];
    }
    __syncthreads();
    int r2 = threadIdx.x >> 3, dbase = (threadIdx.x & 7) * 32;
    float a0 = dts[r2][0], a1 = dts[r2][1], a2 = dts[r2][2], a3 = dts[r2][3];
    float a4 = dts[r2][4], a5 = dts[r2][5], a6 = dts[r2][6], a7 = dts[r2][7];
    size_t drow = (size_t)(row0 + r2) * 256;
#pragma unroll 4
    for (int d = 0; d < 32; d++) {
        const float* wp = dw + (size_t)(dbase + d) * 8;
        float s = db[dbase + d]
                + a0 * wp[0] + a1 * wp[1] + a2 * wp[2] + a3 * wp[3]
                + a4 * wp[4] + a5 * wp[5] + a6 * wp[6] + a7 * wp[7];
        g_dt[drow + dbase + d] = (s > 20.f) ? s : log1pf(__expf(s));
    }
}

// ---------------- selective scan; contract with C only at t=S-1 ----------------
__global__ void scan_kernel(const float* __restrict__ A_log, const float* __restrict__ Dv) {
    int w = blockIdx.x * 8 + (threadIdx.x >> 5);
    int lane = threadIdx.x & 31;
    int bb = w >> 8, d = w & 255;
    float An = -__expf(A_log[d * 32 + lane]);
    float h = 0.f;
#pragma unroll 4
    for (int t = 0; t < 32; t++) {
        size_t bs = (size_t)(bb * 32 + t);
        float dtv = g_dt[bs * 256 + d];
        float uv  = g_u [bs * 256 + d];
        float Bv  = g_xdbl[bs * 72 + 8 + lane];
        h = __expf(dtv * An) * h + (dtv * uv) * Bv;
    }
    size_t bs_last = (size_t)(bb * 32 + 31);
    float Cv = g_xdbl[bs_last * 72 + 40 + lane];
    float y = h * Cv;
#pragma unroll
    for (int o = 16; o; o >>= 1) y += __shfl_xor_sync(0xffffffffu, y, o);
    if (lane == 0) {
        float ul = g_u[bs_last * 256 + d];
        y += Dv[d] * ul;
        float z = g_xz[bs_last * 512 + 256 + d];
        y *= z / (1.f + __expf(-z));
        g_yg[bb * 256 + d] = y;
    }
}

// ---------------- heads: out_proj (last step) + fc1 + fc2 + q ----------------
__global__ void __launch_bounds__(128) heads_kernel(
        const float* __restrict__ op_w,
        const float* __restrict__ fc1_w, const float* __restrict__ fc1_b,
        const float* __restrict__ fc2_w, const float* __restrict__ fc2_b,
        const float* __restrict__ q_w,  const float* __restrict__ q_b,
        float* __restrict__ out) {
    int b = blockIdx.x, tid = threadIdx.x;
    __shared__ float yg[256], lat[128], h1[128], h2[128];
    yg[tid]       = g_yg[b * 256 + tid];
    yg[tid + 128] = g_yg[b * 256 + tid + 128];
    __syncthreads();
    float acc = 0.f;
#pragma unroll 8
    for (int k = 0; k < 256; k++) acc += op_w[tid * 256 + k] * yg[k];
    lat[tid] = acc;
    out[NB * NA + b * 128 + tid] = acc;
    __syncthreads();
    acc = fc1_b[tid];
#pragma unroll 8
    for (int k = 0; k < 128; k++) acc += fc1_w[tid * 128 + k] * lat[k];
    h1[tid] = acc > 0.f ? acc : 0.f;
    __syncthreads();
    acc = fc2_b[tid];
#pragma unroll 8
    for (int k = 0; k < 128; k++) acc += fc2_w[tid * 128 + k] * h1[k];
    h2[tid] = acc > 0.f ? acc : 0.f;
    __syncthreads();
    if (tid < NA) {
        acc = q_b[tid];
#pragma unroll 8
        for (int k = 0; k < 128; k++) acc += q_w[tid * 128 + k] * h2[k];
        out[b * NA + tid] = acc;
    }
}

// ---------------- host launcher ----------------
extern "C" void kernel_launch(void* const* d_in, const int* in_sizes, int n_in,
                              void* d_out, int out_size) {
    const float* x         = (const float*)d_in[0];
    const float* conv1_w   = (const float*)d_in[1];
    const float* conv1_b   = (const float*)d_in[2];
    const float* conv2_w   = (const float*)d_in[3];
    const float* conv2_b   = (const float*)d_in[4];
    const float* conv3_w   = (const float*)d_in[5];
    const float* conv3_b   = (const float*)d_in[6];
    const float* feat_w    = (const float*)d_in[7];
    const float* feat_b    = (const float*)d_in[8];
    const float* in_proj_w = (const float*)d_in[9];
    const float* conv1d_w  = (const float*)d_in[10];
    const float* conv1d_b  = (const float*)d_in[11];
    const float* x_proj_w  = (const float*)d_in[12];
    const float* dt_proj_w = (const float*)d_in[13];
    const float* dt_proj_b = (const float*)d_in[14];
    const float* A_log     = (const float*)d_in[15];
    const float* Dvec      = (const float*)d_in[16];
    const float* out_proj_w= (const float*)d_in[17];
    const float* fc1_w     = (const float*)d_in[18];
    const float* fc1_b     = (const float*)d_in[19];
    const float* fc2_w     = (const float*)d_in[20];
    const float* fc2_b     = (const float*)d_in[21];
    const float* q_w       = (const float*)d_in[22];
    const float* q_b       = (const float*)d_in[23];
    float* out = (float*)d_out;

    cudaFuncSetAttribute(conv1_mma, cudaFuncAttributeMaxDynamicSharedMemorySize, 59136);
    cudaFuncSetAttribute(conv2_mma, cudaFuncAttributeMaxDynamicSharedMemorySize, 64000);
    cudaFuncSetAttribute(conv3_mma, cudaFuncAttributeMaxDynamicSharedMemorySize, 101504);

    prep_wpack<<<532, 256>>>(conv1_w, conv2_w, conv3_w, feat_w, in_proj_w);
    conv1_mma<<<BS * 2, 416, 59136>>>(x, conv1_b);
    conv2_mma<<<BS, 384, 64000>>>(conv2_b);
    conv3_mma<<<BS / 4, 416, 101504>>>(conv3_b);

    // feat: split-K tensor-core GEMM + reduce (emits bf16 hi/lo planes)
    feat_mma<<<dim3(128, 14), 64>>>();
    feat_reduce<<<(BS * 128 + 255) / 256, 256>>>(feat_b);
    // in_proj: tensor-core mma
    inproj_mma<<<dim3(128, 2), 128>>>();
    conv1d_silu<<<(BS * 256 + 255) / 256, 256>>>(conv1d_w, conv1d_b);
    // fused x_proj + dt
    xproj_dt_kernel<<<64, 256>>>(x_proj_w, dt_proj_w, dt_proj_b);
    scan_kernel<<<BS, 256>>>(A_log, Dvec);
    heads_kernel<<<NB, 128>>>(out_proj_w, fc1_w, fc1_b, fc2_w, fc2_b, q_w, q_b, out);
}